// round 1
// baseline (speedup 1.0000x reference)
#include <cuda_runtime.h>
#include <cstdint>

// Problem constants (fixed-shape problem)
#define M_DIM 16384   // B*S = 8*2048
#define N_DIM 4096    // OUT
#define K_DIM 4096    // IN
#define S_LEN 2048
#define R_RANK 16
#define SCALING 2.0f  // alpha/r = 32/16

// ---------------------------------------------------------------------------
// Scratch for t = x @ lora_a^T  (fp32, [M, 16])
// ---------------------------------------------------------------------------
__device__ float g_t[M_DIM * R_RANK];

// ---------------------------------------------------------------------------
// Kernel 1: t[m, r] = sum_k x[m,k] * lora_a[adapter(m)][r][k]
// 8 warps / block, each warp owns 4 rows, lanes stripe K with float4.
// ---------------------------------------------------------------------------
__global__ __launch_bounds__(256) void lora_t_kernel(const float* __restrict__ x,
                                                     const float* __restrict__ la) {
    const int warp = threadIdx.x >> 5;
    const int lane = threadIdx.x & 31;
    const int m0 = blockIdx.x * 32 + warp * 4;
    const int adapter = m0 / S_LEN;  // seg = B/A = 1
    const float* lap = la + (size_t)adapter * R_RANK * K_DIM;

    float acc[4][R_RANK];
#pragma unroll
    for (int rr = 0; rr < 4; rr++)
#pragma unroll
        for (int r = 0; r < R_RANK; r++) acc[rr][r] = 0.f;

    for (int kk = lane; kk < K_DIM / 4; kk += 32) {
        const int k = kk * 4;
        float4 xv[4];
#pragma unroll
        for (int rr = 0; rr < 4; rr++)
            xv[rr] = *(const float4*)(x + (size_t)(m0 + rr) * K_DIM + k);
#pragma unroll
        for (int r = 0; r < R_RANK; r++) {
            const float4 av = *(const float4*)(lap + (size_t)r * K_DIM + k);
#pragma unroll
            for (int rr = 0; rr < 4; rr++) {
                acc[rr][r] += xv[rr].x * av.x;
                acc[rr][r] += xv[rr].y * av.y;
                acc[rr][r] += xv[rr].z * av.z;
                acc[rr][r] += xv[rr].w * av.w;
            }
        }
    }

    // butterfly reduce across the warp
#pragma unroll
    for (int off = 16; off > 0; off >>= 1)
#pragma unroll
        for (int rr = 0; rr < 4; rr++)
#pragma unroll
            for (int r = 0; r < R_RANK; r++)
                acc[rr][r] += __shfl_xor_sync(0xffffffffu, acc[rr][r], off);

    if (lane < R_RANK) {
#pragma unroll
        for (int rr = 0; rr < 4; rr++)
            g_t[(m0 + rr) * R_RANK + lane] = acc[rr][lane];
    }
}

// ---------------------------------------------------------------------------
// Kernel 2: main GEMM (tf32 mma.sync) + fused LoRA epilogue
//   out[m,n] = sum_k x[m,k]*W[n,k]  +  2 * sum_r t[m,r]*lora_b[a][n][r]
// Tiles: 128x128x32, 3-stage cp.async pipeline, 8 warps (2x4), 64x32 per warp.
// ---------------------------------------------------------------------------
#define BM 128
#define BN 128
#define BK 32
#define LDS_T 36                            // padded row stride (floats)
#define STAGES 3
#define STAGE_FLOATS (BM * LDS_T + BN * LDS_T)   // 9216
#define SMEM_BYTES (STAGES * STAGE_FLOATS * 4)   // 110592

__device__ __forceinline__ uint32_t f2tf32(float f) {
    uint32_t u;
    asm("cvt.rna.tf32.f32 %0, %1;" : "=r"(u) : "f"(f));
    return u;
}

__device__ __forceinline__ void mma_tf32(float* c, const uint32_t* a, const uint32_t* b) {
    asm volatile(
        "mma.sync.aligned.m16n8k8.row.col.f32.tf32.tf32.f32 "
        "{%0,%1,%2,%3}, {%4,%5,%6,%7}, {%8,%9}, {%0,%1,%2,%3};"
        : "+f"(c[0]), "+f"(c[1]), "+f"(c[2]), "+f"(c[3])
        : "r"(a[0]), "r"(a[1]), "r"(a[2]), "r"(a[3]), "r"(b[0]), "r"(b[1]));
}

__global__ __launch_bounds__(256, 2) void lora_gemm_kernel(
    const float* __restrict__ x, const float* __restrict__ W,
    const float* __restrict__ lb, float* __restrict__ out) {
    extern __shared__ float smem[];
    const int tid = threadIdx.x;
    const int lane = tid & 31;
    const int warp = tid >> 5;
    const int warp_m = warp >> 2;  // 0..1 -> 64 rows each
    const int warp_n = warp & 3;   // 0..3 -> 32 cols each
    const int g = lane >> 2;       // groupID 0..7
    const int tg = lane & 3;       // thread-in-group 0..3
    const int m0 = blockIdx.y * BM;
    const int n0 = blockIdx.x * BN;

    float acc[4][4][4];
#pragma unroll
    for (int mt = 0; mt < 4; mt++)
#pragma unroll
        for (int nt = 0; nt < 4; nt++)
#pragma unroll
            for (int c = 0; c < 4; c++) acc[mt][nt][c] = 0.f;

    auto load_tile = [&](int stage, int kt) {
        float* As = smem + stage * STAGE_FLOATS;
        float* Bs = As + BM * LDS_T;
        const int kbase = kt * BK;
#pragma unroll
        for (int i = 0; i < 4; i++) {
            const int id = tid + i * 256;        // 0..1023 f4 slots
            const int row = id >> 3;             // 0..127
            const int kc = (id & 7) * 4;         // 0..28
            const float* gA = x + (size_t)(m0 + row) * K_DIM + kbase + kc;
            uint32_t dA = (uint32_t)__cvta_generic_to_shared(&As[row * LDS_T + kc]);
            asm volatile("cp.async.cg.shared.global [%0], [%1], 16;" ::"r"(dA), "l"(gA));
            const float* gB = W + (size_t)(n0 + row) * K_DIM + kbase + kc;
            uint32_t dB = (uint32_t)__cvta_generic_to_shared(&Bs[row * LDS_T + kc]);
            asm volatile("cp.async.cg.shared.global [%0], [%1], 16;" ::"r"(dB), "l"(gB));
        }
    };

    auto compute_tile = [&](int stage) {
        const float* As = smem + stage * STAGE_FLOATS;
        const float* Bs = As + BM * LDS_T;
#pragma unroll
        for (int ks = 0; ks < 4; ks++) {
            const int kb = ks * 8;
            uint32_t af[4][4];
#pragma unroll
            for (int mt = 0; mt < 4; mt++) {
                const int r0 = warp_m * 64 + mt * 16 + g;
                af[mt][0] = f2tf32(As[r0 * LDS_T + kb + tg]);
                af[mt][1] = f2tf32(As[(r0 + 8) * LDS_T + kb + tg]);
                af[mt][2] = f2tf32(As[r0 * LDS_T + kb + tg + 4]);
                af[mt][3] = f2tf32(As[(r0 + 8) * LDS_T + kb + tg + 4]);
            }
            uint32_t bf[4][2];
#pragma unroll
            for (int nt = 0; nt < 4; nt++) {
                const int c0 = warp_n * 32 + nt * 8 + g;
                bf[nt][0] = f2tf32(Bs[c0 * LDS_T + kb + tg]);
                bf[nt][1] = f2tf32(Bs[c0 * LDS_T + kb + tg + 4]);
            }
#pragma unroll
            for (int mt = 0; mt < 4; mt++)
#pragma unroll
                for (int nt = 0; nt < 4; nt++)
                    mma_tf32(acc[mt][nt], af[mt], bf[nt]);
        }
    };

    // --- pipelined mainloop ---
#pragma unroll
    for (int s = 0; s < STAGES - 1; s++) {
        load_tile(s, s);
        asm volatile("cp.async.commit_group;");
    }
    const int KT = K_DIM / BK;  // 128
    for (int kt = 0; kt < KT; kt++) {
        asm volatile("cp.async.wait_group %0;" ::"n"(STAGES - 2));
        __syncthreads();
        const int nxt = kt + STAGES - 1;
        if (nxt < KT) load_tile(nxt % STAGES, nxt);
        asm volatile("cp.async.commit_group;");
        compute_tile(kt % STAGES);
    }

    // --- fused LoRA epilogue: acc += 2 * t[m,:] . lora_b[a][n,:] ---
    __syncthreads();
    float* Ts = smem;                 // [128][16]
    float* Ls = smem + BM * R_RANK;   // [128][16]
    const int adapter = m0 / S_LEN;   // BM=128 divides S=2048 -> uniform per block
    for (int id = tid; id < BM * 4; id += 256) {
        const int row = id >> 2, c = (id & 3) * 4;
        *(float4*)&Ts[row * R_RANK + c] = *(const float4*)&g_t[(m0 + row) * R_RANK + c];
    }
    for (int id = tid; id < BN * 4; id += 256) {
        const int row = id >> 2, c = (id & 3) * 4;
        *(float4*)&Ls[row * R_RANK + c] =
            *(const float4*)&lb[((size_t)adapter * N_DIM + (n0 + row)) * R_RANK + c];
    }
    __syncthreads();

#pragma unroll
    for (int rg = 0; rg < 4; rg++) {
        float4 lv[8];
#pragma unroll
        for (int nt = 0; nt < 4; nt++)
#pragma unroll
            for (int j = 0; j < 2; j++) {
                const int col = warp_n * 32 + nt * 8 + tg * 2 + j;
                lv[nt * 2 + j] = *(float4*)&Ls[col * R_RANK + rg * 4];
            }
#pragma unroll
        for (int mt = 0; mt < 4; mt++)
#pragma unroll
            for (int i = 0; i < 2; i++) {
                const int row = warp_m * 64 + mt * 16 + g + i * 8;
                const float4 tv = *(float4*)&Ts[row * R_RANK + rg * 4];
#pragma unroll
                for (int nt = 0; nt < 4; nt++)
#pragma unroll
                    for (int j = 0; j < 2; j++) {
                        const float4 l = lv[nt * 2 + j];
                        float d = tv.x * l.x + tv.y * l.y + tv.z * l.z + tv.w * l.w;
                        acc[mt][nt][i * 2 + j] += SCALING * d;
                    }
            }
    }

    // --- store ---
#pragma unroll
    for (int mt = 0; mt < 4; mt++)
#pragma unroll
        for (int i = 0; i < 2; i++) {
            const int row = m0 + warp_m * 64 + mt * 16 + g + i * 8;
#pragma unroll
            for (int nt = 0; nt < 4; nt++) {
                const int col = n0 + warp_n * 32 + nt * 8 + tg * 2;
                float2 v = make_float2(acc[mt][nt][i * 2 + 0], acc[mt][nt][i * 2 + 1]);
                *(float2*)&out[(size_t)row * N_DIM + col] = v;
            }
        }
}

// ---------------------------------------------------------------------------
// Harness entry point
// Inputs: d_in[0]=data [8,2048,4096] f32, d_in[1]=W [4096,4096] f32,
//         d_in[2]=lora_a [8,16,4096] f32, d_in[3]=lora_b [8,4096,16] f32
// Output: [8,2048,4096] f32
// ---------------------------------------------------------------------------
extern "C" void kernel_launch(void* const* d_in, const int* in_sizes, int n_in,
                              void* d_out, int out_size) {
    const float* x = (const float*)d_in[0];
    const float* W = (const float*)d_in[1];
    const float* la = (const float*)d_in[2];
    const float* lb = (const float*)d_in[3];
    float* out = (float*)d_out;

    cudaFuncSetAttribute(lora_gemm_kernel,
                         cudaFuncAttributeMaxDynamicSharedMemorySize, SMEM_BYTES);

    lora_t_kernel<<<M_DIM / 32, 256>>>(x, la);

    dim3 grid(N_DIM / BN, M_DIM / BM);  // (32, 128)
    lora_gemm_kernel<<<grid, 256, SMEM_BYTES>>>(x, W, lb, out);
}

// round 4
// speedup vs baseline: 1.3893x; 1.3893x over previous
#include <cuda_runtime.h>
#include <cstdint>

// ---------------------------------------------------------------------------
// Problem constants
// ---------------------------------------------------------------------------
#define M_DIM 16384   // B*S = 8*2048
#define N_DIM 4096    // OUT
#define K_DIM 4096    // IN
#define KE    4224    // extended K: 4096 + 8 adapters * 16 rank
#define KT_CNT 132    // KE / 32
#define S_LEN 2048
#define R_RANK 16

// ---------------------------------------------------------------------------
// Device-global scratch (module-load allocated; no runtime alloc)
//  g_t  : t = x @ lora_a^T, fp32 [M, 16]
//  g_xe : A image, tf32-rounded + K-extended + FRAGMENT-PACKED
//         [mtile(128)][ktile(132)] x 16KB tiles; tile unit u (16B):
//         u = ((wm*4+mt)*4+ks)*32 + lane ; unit = {A[g][tg],A[g+8][tg],
//         A[g][tg+4],A[g+8][tg+4]} rows rel. wm*64+mt*16, k rel. ks*8
//  g_we : B image, same idea: [ntile(32)][ktile(132)] x 16KB tiles;
//         u = ((wn*2+ntp)*4+ks)*32 + lane ; unit = {W[ne][tg],W[ne][tg+4],
//         W[ne+8][tg],W[ne+8][tg+4]}, ne = wn*32+ntp*16+g
// ---------------------------------------------------------------------------
__device__ float g_t[M_DIM * R_RANK];
__device__ __align__(1024) float g_xe[(size_t)128 * KT_CNT * 4096];
__device__ __align__(1024) float g_we[(size_t)32  * KT_CNT * 4096];

__device__ __forceinline__ float rna(float f) {
    uint32_t u;
    asm("cvt.rna.tf32.f32 %0, %1;" : "=r"(u) : "f"(f));
    return __uint_as_float(u);
}

// ---------------------------------------------------------------------------
// Kernel 1: t[m, r] = sum_k x[m,k] * lora_a[adapter(m)][r][k]   (fp32 exact)
// ---------------------------------------------------------------------------
__global__ __launch_bounds__(256) void lora_t_kernel(const float* __restrict__ x,
                                                     const float* __restrict__ la) {
    const int warp = threadIdx.x >> 5;
    const int lane = threadIdx.x & 31;
    const int m0 = blockIdx.x * 32 + warp * 4;
    const int adapter = m0 / S_LEN;
    const float* lap = la + (size_t)adapter * R_RANK * K_DIM;

    float acc[4][R_RANK];
#pragma unroll
    for (int rr = 0; rr < 4; rr++)
#pragma unroll
        for (int r = 0; r < R_RANK; r++) acc[rr][r] = 0.f;

    for (int kk = lane; kk < K_DIM / 4; kk += 32) {
        const int k = kk * 4;
        float4 xv[4];
#pragma unroll
        for (int rr = 0; rr < 4; rr++)
            xv[rr] = *(const float4*)(x + (size_t)(m0 + rr) * K_DIM + k);
#pragma unroll
        for (int r = 0; r < R_RANK; r++) {
            const float4 av = *(const float4*)(lap + (size_t)r * K_DIM + k);
#pragma unroll
            for (int rr = 0; rr < 4; rr++) {
                acc[rr][r] += xv[rr].x * av.x;
                acc[rr][r] += xv[rr].y * av.y;
                acc[rr][r] += xv[rr].z * av.z;
                acc[rr][r] += xv[rr].w * av.w;
            }
        }
    }
#pragma unroll
    for (int off = 16; off > 0; off >>= 1)
#pragma unroll
        for (int rr = 0; rr < 4; rr++)
#pragma unroll
            for (int r = 0; r < R_RANK; r++)
                acc[rr][r] += __shfl_xor_sync(0xffffffffu, acc[rr][r], off);
    if (lane < R_RANK) {
#pragma unroll
        for (int rr = 0; rr < 4; rr++)
            g_t[(m0 + rr) * R_RANK + lane] = acc[rr][lane];
    }
}

// ---------------------------------------------------------------------------
// Kernel 2: build A image (fragment-packed, tf32-rounded, K-extended)
// one thread = one 16B unit; writes fully coalesced
// ---------------------------------------------------------------------------
__global__ __launch_bounds__(256) void ext_a_kernel(const float* __restrict__ x) {
    const uint32_t idx = blockIdx.x * 256 + threadIdx.x;  // < 128*132*1024
    const uint32_t u = idx & 1023;
    const uint32_t tile = idx >> 10;
    const uint32_t mtile = tile / KT_CNT;
    const uint32_t ktile = tile % KT_CNT;

    const uint32_t lane = u & 31;
    const uint32_t ks = (u >> 5) & 3;
    const uint32_t mt = (u >> 7) & 3;
    const uint32_t wm = (u >> 9) & 1;
    const uint32_t g = lane >> 2, tg = lane & 3;

    const uint32_t m0 = mtile * 128 + wm * 64 + mt * 16 + g;  // rows m0, m0+8
    const uint32_t k = ktile * 32 + ks * 8 + tg;              // k, k+4

    float4 v;
    if (k < K_DIM) {
        v.x = rna(x[(size_t)m0 * K_DIM + k]);
        v.y = rna(x[(size_t)(m0 + 8) * K_DIM + k]);
        v.z = rna(x[(size_t)m0 * K_DIM + k + 4]);
        v.w = rna(x[(size_t)(m0 + 8) * K_DIM + k + 4]);
    } else {
        const uint32_t e0 = k - K_DIM, e1 = k + 4 - K_DIM;
        const uint32_t a0 = e0 >> 4, r0 = e0 & 15;
        const uint32_t a1 = e1 >> 4, r1 = e1 & 15;
        const uint32_t ad = m0 >> 11;  // adapter, uniform over the 128-row tile
        v.x = (a0 == ad) ? rna(2.0f * g_t[m0 * R_RANK + r0]) : 0.f;
        v.y = (a0 == ad) ? rna(2.0f * g_t[(m0 + 8) * R_RANK + r0]) : 0.f;
        v.z = (a1 == ad) ? rna(2.0f * g_t[m0 * R_RANK + r1]) : 0.f;
        v.w = (a1 == ad) ? rna(2.0f * g_t[(m0 + 8) * R_RANK + r1]) : 0.f;
    }
    *(float4*)(g_xe + ((size_t)tile << 12) + u * 4) = v;
}

// ---------------------------------------------------------------------------
// Kernel 3: build B image (fragment-packed, tf32-rounded, K-extended)
// ---------------------------------------------------------------------------
__global__ __launch_bounds__(256) void ext_b_kernel(const float* __restrict__ W,
                                                    const float* __restrict__ lb) {
    const uint32_t idx = blockIdx.x * 256 + threadIdx.x;  // < 32*132*1024
    const uint32_t u = idx & 1023;
    const uint32_t tile = idx >> 10;
    const uint32_t ntile = tile / KT_CNT;
    const uint32_t ktile = tile % KT_CNT;

    const uint32_t lane = u & 31;
    const uint32_t ks = (u >> 5) & 3;
    const uint32_t ntp = (u >> 7) & 1;
    const uint32_t wn = (u >> 8) & 3;
    const uint32_t g = lane >> 2, tg = lane & 3;

    const uint32_t ne = ntile * 128 + wn * 32 + ntp * 16 + g;  // cols ne, ne+8
    const uint32_t k = ktile * 32 + ks * 8 + tg;               // k, k+4

    float4 v;
    if (k < K_DIM) {
        v.x = rna(W[(size_t)ne * K_DIM + k]);
        v.y = rna(W[(size_t)ne * K_DIM + k + 4]);
        v.z = rna(W[(size_t)(ne + 8) * K_DIM + k]);
        v.w = rna(W[(size_t)(ne + 8) * K_DIM + k + 4]);
    } else {
        const uint32_t e0 = k - K_DIM, e1 = k + 4 - K_DIM;
        const uint32_t a0 = e0 >> 4, r0 = e0 & 15;
        const uint32_t a1 = e1 >> 4, r1 = e1 & 15;
        v.x = rna(lb[((size_t)a0 * N_DIM + ne) * R_RANK + r0]);
        v.y = rna(lb[((size_t)a1 * N_DIM + ne) * R_RANK + r1]);
        v.z = rna(lb[((size_t)a0 * N_DIM + ne + 8) * R_RANK + r0]);
        v.w = rna(lb[((size_t)a1 * N_DIM + ne + 8) * R_RANK + r1]);
    }
    *(float4*)(g_we + ((size_t)tile << 12) + u * 4) = v;
}

// ---------------------------------------------------------------------------
// Kernel 4: GEMM. 128x128x32 tiles, tf32 mma.sync, fragment-packed smem,
// 3-stage cp.async pipeline. Mainloop = 24 LDS.128 + 64 MMA per warp-ktile.
// ---------------------------------------------------------------------------
#define BM 128
#define BN 128
#define BK 32
#define STAGES 3
#define TILE_BYTES 16384
#define STAGE_BYTES (2 * TILE_BYTES)               // A + B
#define SMEM_BYTES (STAGES * STAGE_BYTES)          // 98304

__device__ __forceinline__ void mma_tf32(float* c, const uint32_t* a, const uint32_t* b) {
    asm volatile(
        "mma.sync.aligned.m16n8k8.row.col.f32.tf32.tf32.f32 "
        "{%0,%1,%2,%3}, {%4,%5,%6,%7}, {%8,%9}, {%0,%1,%2,%3};"
        : "+f"(c[0]), "+f"(c[1]), "+f"(c[2]), "+f"(c[3])
        : "r"(a[0]), "r"(a[1]), "r"(a[2]), "r"(a[3]), "r"(b[0]), "r"(b[1]));
}

__global__ __launch_bounds__(256, 2) void lora_gemm_kernel(float* __restrict__ out) {
    extern __shared__ char smem[];
    const int tid = threadIdx.x;
    const int lane = tid & 31;
    const int warp = tid >> 5;
    const int warp_m = warp >> 2;   // 0..1
    const int warp_n = warp & 3;    // 0..3
    const int g = lane >> 2;
    const int tg = lane & 3;
    const uint32_t mtile = blockIdx.y;
    const uint32_t ntile = blockIdx.x;

    float acc[4][4][4];
#pragma unroll
    for (int mt = 0; mt < 4; mt++)
#pragma unroll
        for (int nt = 0; nt < 4; nt++)
#pragma unroll
            for (int c = 0; c < 4; c++) acc[mt][nt][c] = 0.f;

    const char* gA = (const char*)g_xe + ((size_t)mtile * KT_CNT << 14);
    const char* gB = (const char*)g_we + ((size_t)ntile * KT_CNT << 14);

    auto load_tile = [&](int stage, int kt) {
        char* st = smem + stage * STAGE_BYTES;
        const char* sa = gA + ((size_t)kt << 14);
        const char* sb = gB + ((size_t)kt << 14);
#pragma unroll
        for (int i = 0; i < 4; i++) {
            const int off = (tid + i * 256) * 16;
            uint32_t dA = (uint32_t)__cvta_generic_to_shared(st + off);
            asm volatile("cp.async.cg.shared.global [%0], [%1], 16;" ::"r"(dA), "l"(sa + off));
            uint32_t dB = (uint32_t)__cvta_generic_to_shared(st + TILE_BYTES + off);
            asm volatile("cp.async.cg.shared.global [%0], [%1], 16;" ::"r"(dB), "l"(sb + off));
        }
    };

    auto compute_tile = [&](int stage) {
        const char* sA = smem + stage * STAGE_BYTES;
        const char* sB = sA + TILE_BYTES;
#pragma unroll
        for (int ks = 0; ks < 4; ks++) {
            uint4 af[4];
#pragma unroll
            for (int mt = 0; mt < 4; mt++)
                af[mt] = *(const uint4*)(sA + (((warp_m * 4 + mt) * 4 + ks) * 32 + lane) * 16);
            uint4 bv[2];
#pragma unroll
            for (int ntp = 0; ntp < 2; ntp++)
                bv[ntp] = *(const uint4*)(sB + (((warp_n * 2 + ntp) * 4 + ks) * 32 + lane) * 16);
            uint32_t bf[4][2];
#pragma unroll
            for (int ntp = 0; ntp < 2; ntp++) {
                bf[2 * ntp][0] = bv[ntp].x;
                bf[2 * ntp][1] = bv[ntp].y;
                bf[2 * ntp + 1][0] = bv[ntp].z;
                bf[2 * ntp + 1][1] = bv[ntp].w;
            }
#pragma unroll
            for (int mt = 0; mt < 4; mt++)
#pragma unroll
                for (int nt = 0; nt < 4; nt++)
                    mma_tf32(acc[mt][nt], (const uint32_t*)&af[mt], bf[nt]);
        }
    };

#pragma unroll
    for (int s = 0; s < STAGES - 1; s++) {
        load_tile(s, s);
        asm volatile("cp.async.commit_group;");
    }
    for (int kt = 0; kt < KT_CNT; kt++) {
        asm volatile("cp.async.wait_group %0;" ::"n"(STAGES - 2));
        __syncthreads();
        const int nxt = kt + STAGES - 1;
        if (nxt < KT_CNT) load_tile(nxt % STAGES, nxt);
        asm volatile("cp.async.commit_group;");
        compute_tile(kt % STAGES);
    }

    // ---- pure-store epilogue (LoRA already folded into K) ----
#pragma unroll
    for (int mt = 0; mt < 4; mt++)
#pragma unroll
        for (int i = 0; i < 2; i++) {
            const size_t row = (size_t)mtile * BM + warp_m * 64 + mt * 16 + g + i * 8;
#pragma unroll
            for (int nt = 0; nt < 4; nt++) {
                const uint32_t col = ntile * BN + warp_n * 32 + nt * 8 + tg * 2;
                *(float2*)&out[row * N_DIM + col] =
                    make_float2(acc[mt][nt][i * 2 + 0], acc[mt][nt][i * 2 + 1]);
            }
        }
}

// ---------------------------------------------------------------------------
// Harness entry
// d_in[0]=data [8,2048,4096] f32, d_in[1]=W [4096,4096] f32,
// d_in[2]=lora_a [8,16,4096] f32, d_in[3]=lora_b [8,4096,16] f32
// ---------------------------------------------------------------------------
extern "C" void kernel_launch(void* const* d_in, const int* in_sizes, int n_in,
                              void* d_out, int out_size) {
    const float* x = (const float*)d_in[0];
    const float* W = (const float*)d_in[1];
    const float* la = (const float*)d_in[2];
    const float* lb = (const float*)d_in[3];
    float* out = (float*)d_out;

    cudaFuncSetAttribute(lora_gemm_kernel,
                         cudaFuncAttributeMaxDynamicSharedMemorySize, SMEM_BYTES);

    lora_t_kernel<<<M_DIM / 32, 256>>>(x, la);
    ext_a_kernel<<<(128 * KT_CNT * 1024) / 256, 256>>>(x);
    ext_b_kernel<<<(32 * KT_CNT * 1024) / 256, 256>>>(W, lb);

    dim3 grid(N_DIM / BN, M_DIM / BM);  // (32, 128)
    lora_gemm_kernel<<<grid, 256, SMEM_BYTES>>>(out);
}

// round 6
// speedup vs baseline: 2.5699x; 1.8497x over previous
#include <cuda_runtime.h>
#include <cuda_fp16.h>
#include <cstdint>

// ---------------------------------------------------------------------------
// Problem constants
// ---------------------------------------------------------------------------
#define M_DIM 16384   // B*S = 8*2048
#define N_DIM 4096    // OUT
#define K_DIM 4096    // IN
#define KE    4224    // extended K: 4096 + 8 adapters * 16 rank
#define BK    64
#define KT_CNT 66     // KE / 64
#define S_LEN 2048
#define R_RANK 16

// ---------------------------------------------------------------------------
// Device-global scratch
//  g_t  : t = x @ lora_a^T, fp32 [M, 16]
//  g_xe : A image, fp16 + K-extended + FRAGMENT-PACKED (m16n8k16 layout)
//         [mtile(128)][ktile(66)] x 16KB tiles (8192 halves)
//         unit u = ((wm*4+mt)*4+ks)*32+lane, 16B = regs a0..a3 of the
//         m16n8k16 A fragment for rows wm*64+mt*16+{g,g+8}, k=ks*16+2tg..
//  g_we : B image likewise: [ntile(32)][ktile(66)] x 16KB tiles
//         unit u = ((wn*2+ntp)*4+ks)*32+lane = {b0,b1 of nt=2ntp; b0,b1 of
//         nt=2ntp+1} for cols wn*32+ntp*16+{g,g+8}
// ---------------------------------------------------------------------------
__device__ float g_t[M_DIM * R_RANK];
__device__ __align__(1024) __half g_xe[(size_t)128 * KT_CNT * 8192];
__device__ __align__(1024) __half g_we[(size_t)32  * KT_CNT * 8192];

__device__ __forceinline__ uint32_t pack2(float lo, float hi) {
    __half2 h = __floats2half2_rn(lo, hi);   // .x = lo (low half = first k)
    return *(uint32_t*)&h;
}

// ---------------------------------------------------------------------------
// Kernel 1: t[m, r] = sum_k x[m,k] * lora_a[adapter(m)][r][k]   (fp32 exact)
// ---------------------------------------------------------------------------
__global__ __launch_bounds__(256) void lora_t_kernel(const float* __restrict__ x,
                                                     const float* __restrict__ la) {
    const int warp = threadIdx.x >> 5;
    const int lane = threadIdx.x & 31;
    const int m0 = blockIdx.x * 32 + warp * 4;
    const int adapter = m0 / S_LEN;
    const float* lap = la + (size_t)adapter * R_RANK * K_DIM;

    float acc[4][R_RANK];
#pragma unroll
    for (int rr = 0; rr < 4; rr++)
#pragma unroll
        for (int r = 0; r < R_RANK; r++) acc[rr][r] = 0.f;

    for (int kk = lane; kk < K_DIM / 4; kk += 32) {
        const int k = kk * 4;
        float4 xv[4];
#pragma unroll
        for (int rr = 0; rr < 4; rr++)
            xv[rr] = *(const float4*)(x + (size_t)(m0 + rr) * K_DIM + k);
#pragma unroll
        for (int r = 0; r < R_RANK; r++) {
            const float4 av = *(const float4*)(lap + (size_t)r * K_DIM + k);
#pragma unroll
            for (int rr = 0; rr < 4; rr++) {
                acc[rr][r] += xv[rr].x * av.x;
                acc[rr][r] += xv[rr].y * av.y;
                acc[rr][r] += xv[rr].z * av.z;
                acc[rr][r] += xv[rr].w * av.w;
            }
        }
    }
#pragma unroll
    for (int off = 16; off > 0; off >>= 1)
#pragma unroll
        for (int rr = 0; rr < 4; rr++)
#pragma unroll
            for (int r = 0; r < R_RANK; r++)
                acc[rr][r] += __shfl_xor_sync(0xffffffffu, acc[rr][r], off);
    if (lane < R_RANK) {
#pragma unroll
        for (int rr = 0; rr < 4; rr++)
            g_t[(m0 + rr) * R_RANK + lane] = acc[rr][lane];
    }
}

// ---------------------------------------------------------------------------
// Kernel 2: build A image (fp16, fragment-packed, K-extended)
// one thread = one 16B unit (= one A fragment: a0..a3)
// ---------------------------------------------------------------------------
__global__ __launch_bounds__(256) void ext_a_kernel(const float* __restrict__ x) {
    const uint32_t idx = blockIdx.x * 256 + threadIdx.x;  // < 128*66*1024
    const uint32_t u = idx & 1023;
    const uint32_t tile = idx >> 10;
    const uint32_t mtile = tile / KT_CNT;
    const uint32_t ktile = tile % KT_CNT;

    const uint32_t lane = u & 31;
    const uint32_t ks = (u >> 5) & 3;
    const uint32_t mt = (u >> 7) & 3;
    const uint32_t wm = (u >> 9) & 1;
    const uint32_t g = lane >> 2, tg = lane & 3;

    const uint32_t m0 = mtile * 128 + wm * 64 + mt * 16 + g;  // rows m0, m0+8
    const uint32_t k0 = ktile * 64 + ks * 16 + 2 * tg;        // k0,k0+1,k0+8,k0+9

    uint4 v;
    if (k0 < K_DIM) {
        const float2 p00 = *(const float2*)(x + (size_t)m0 * K_DIM + k0);
        const float2 p10 = *(const float2*)(x + (size_t)(m0 + 8) * K_DIM + k0);
        const float2 p01 = *(const float2*)(x + (size_t)m0 * K_DIM + k0 + 8);
        const float2 p11 = *(const float2*)(x + (size_t)(m0 + 8) * K_DIM + k0 + 8);
        v.x = pack2(p00.x, p00.y);
        v.y = pack2(p10.x, p10.y);
        v.z = pack2(p01.x, p01.y);
        v.w = pack2(p11.x, p11.y);
    } else {
        const uint32_t e = k0 - K_DIM;        // pairs stay inside one 16-chunk
        const uint32_t a = e >> 4, r = e & 15;
        const uint32_t ad = m0 >> 11;         // adapter uniform over the tile
        if (a == ad) {
            const float2 t00 = *(const float2*)(g_t + m0 * R_RANK + r);
            const float2 t10 = *(const float2*)(g_t + (m0 + 8) * R_RANK + r);
            const float2 t01 = *(const float2*)(g_t + m0 * R_RANK + r + 8);
            const float2 t11 = *(const float2*)(g_t + (m0 + 8) * R_RANK + r + 8);
            v.x = pack2(2.f * t00.x, 2.f * t00.y);
            v.y = pack2(2.f * t10.x, 2.f * t10.y);
            v.z = pack2(2.f * t01.x, 2.f * t01.y);
            v.w = pack2(2.f * t11.x, 2.f * t11.y);
        } else {
            v = make_uint4(0, 0, 0, 0);
        }
    }
    *(uint4*)(g_xe + (size_t)tile * 8192 + u * 8) = v;
}

// ---------------------------------------------------------------------------
// Kernel 3: build B image (fp16, fragment-packed, K-extended)
// unit = {b0,b1}(col c0) ++ {b0,b1}(col c0+8)
// ---------------------------------------------------------------------------
__global__ __launch_bounds__(256) void ext_b_kernel(const float* __restrict__ W,
                                                    const float* __restrict__ lb) {
    const uint32_t idx = blockIdx.x * 256 + threadIdx.x;  // < 32*66*1024
    const uint32_t u = idx & 1023;
    const uint32_t tile = idx >> 10;
    const uint32_t ntile = tile / KT_CNT;
    const uint32_t ktile = tile % KT_CNT;

    const uint32_t lane = u & 31;
    const uint32_t ks = (u >> 5) & 3;
    const uint32_t ntp = (u >> 7) & 1;
    const uint32_t wn = (u >> 8) & 3;
    const uint32_t g = lane >> 2, tg = lane & 3;

    const uint32_t c0 = ntile * 128 + wn * 32 + ntp * 16 + g;  // cols c0, c0+8
    const uint32_t k0 = ktile * 64 + ks * 16 + 2 * tg;

    uint4 v;
    if (k0 < K_DIM) {
        const float2 p00 = *(const float2*)(W + (size_t)c0 * K_DIM + k0);
        const float2 p01 = *(const float2*)(W + (size_t)c0 * K_DIM + k0 + 8);
        const float2 p10 = *(const float2*)(W + (size_t)(c0 + 8) * K_DIM + k0);
        const float2 p11 = *(const float2*)(W + (size_t)(c0 + 8) * K_DIM + k0 + 8);
        v.x = pack2(p00.x, p00.y);   // b0 col c0
        v.y = pack2(p01.x, p01.y);   // b1 col c0
        v.z = pack2(p10.x, p10.y);   // b0 col c0+8
        v.w = pack2(p11.x, p11.y);   // b1 col c0+8
    } else {
        const uint32_t e = k0 - K_DIM;
        const uint32_t a = e >> 4, r = e & 15;
        const float* p0 = lb + ((size_t)a * N_DIM + c0) * R_RANK;
        const float* p1 = lb + ((size_t)a * N_DIM + c0 + 8) * R_RANK;
        v.x = pack2(p0[r], p0[r + 1]);
        v.y = pack2(p0[r + 8], p0[r + 9]);
        v.z = pack2(p1[r], p1[r + 1]);
        v.w = pack2(p1[r + 8], p1[r + 9]);
    }
    *(uint4*)(g_we + (size_t)tile * 8192 + u * 8) = v;
}

// ---------------------------------------------------------------------------
// Kernel 4: GEMM. 128x128x64 tiles, fp16 m16n8k16 mma.sync (f32 accum),
// fragment-packed smem, 3-stage cp.async pipeline.
// Per warp-ktile: 24 LDS.128 + 64 MMA.
// ---------------------------------------------------------------------------
#define STAGES 3
#define TILE_BYTES 16384
#define STAGE_BYTES (2 * TILE_BYTES)          // A + B = 32KB
#define SMEM_BYTES (STAGES * STAGE_BYTES)     // 98304

__device__ __forceinline__ void mma_f16(float* c, const uint32_t* a, const uint32_t* b) {
    asm volatile(
        "mma.sync.aligned.m16n8k16.row.col.f32.f16.f16.f32 "
        "{%0,%1,%2,%3}, {%4,%5,%6,%7}, {%8,%9}, {%0,%1,%2,%3};"
        : "+f"(c[0]), "+f"(c[1]), "+f"(c[2]), "+f"(c[3])
        : "r"(a[0]), "r"(a[1]), "r"(a[2]), "r"(a[3]), "r"(b[0]), "r"(b[1]));
}

__global__ __launch_bounds__(256, 2) void lora_gemm_kernel(float* __restrict__ out) {
    extern __shared__ char smem[];
    const int tid = threadIdx.x;
    const int lane = tid & 31;
    const int warp = tid >> 5;
    const int warp_m = warp >> 2;   // 0..1
    const int warp_n = warp & 3;    // 0..3
    const int g = lane >> 2;
    const int tg = lane & 3;
    const uint32_t mtile = blockIdx.y;
    const uint32_t ntile = blockIdx.x;

    float acc[4][4][4];
#pragma unroll
    for (int mt = 0; mt < 4; mt++)
#pragma unroll
        for (int nt = 0; nt < 4; nt++)
#pragma unroll
            for (int c = 0; c < 4; c++) acc[mt][nt][c] = 0.f;

    const char* gA = (const char*)g_xe + ((size_t)mtile * KT_CNT << 14);
    const char* gB = (const char*)g_we + ((size_t)ntile * KT_CNT << 14);

    auto load_tile = [&](int stage, int kt) {
        char* st = smem + stage * STAGE_BYTES;
        const char* sa = gA + ((size_t)kt << 14);
        const char* sb = gB + ((size_t)kt << 14);
#pragma unroll
        for (int i = 0; i < 4; i++) {
            const int off = (tid + i * 256) * 16;
            uint32_t dA = (uint32_t)__cvta_generic_to_shared(st + off);
            asm volatile("cp.async.cg.shared.global [%0], [%1], 16;" ::"r"(dA), "l"(sa + off));
            uint32_t dB = (uint32_t)__cvta_generic_to_shared(st + TILE_BYTES + off);
            asm volatile("cp.async.cg.shared.global [%0], [%1], 16;" ::"r"(dB), "l"(sb + off));
        }
    };

    auto compute_tile = [&](int stage) {
        const char* sA = smem + stage * STAGE_BYTES;
        const char* sB = sA + TILE_BYTES;
#pragma unroll
        for (int ks = 0; ks < 4; ks++) {
            uint4 af[4];
#pragma unroll
            for (int mt = 0; mt < 4; mt++)
                af[mt] = *(const uint4*)(sA + (((warp_m * 4 + mt) * 4 + ks) * 32 + lane) * 16);
            uint4 bv[2];
#pragma unroll
            for (int ntp = 0; ntp < 2; ntp++)
                bv[ntp] = *(const uint4*)(sB + (((warp_n * 2 + ntp) * 4 + ks) * 32 + lane) * 16);
            uint32_t bf[4][2];
#pragma unroll
            for (int ntp = 0; ntp < 2; ntp++) {
                bf[2 * ntp][0] = bv[ntp].x;
                bf[2 * ntp][1] = bv[ntp].y;
                bf[2 * ntp + 1][0] = bv[ntp].z;
                bf[2 * ntp + 1][1] = bv[ntp].w;
            }
#pragma unroll
            for (int mt = 0; mt < 4; mt++)
#pragma unroll
                for (int nt = 0; nt < 4; nt++)
                    mma_f16(acc[mt][nt], (const uint32_t*)&af[mt], bf[nt]);
        }
    };

#pragma unroll
    for (int s = 0; s < STAGES - 1; s++) {
        load_tile(s, s);
        asm volatile("cp.async.commit_group;");
    }
    for (int kt = 0; kt < KT_CNT; kt++) {
        asm volatile("cp.async.wait_group %0;" ::"n"(STAGES - 2));
        __syncthreads();
        const int nxt = kt + STAGES - 1;
        if (nxt < KT_CNT) load_tile(nxt % STAGES, nxt);
        asm volatile("cp.async.commit_group;");
        compute_tile(kt % STAGES);
    }

    // ---- pure-store epilogue (LoRA already folded into K) ----
#pragma unroll
    for (int mt = 0; mt < 4; mt++)
#pragma unroll
        for (int i = 0; i < 2; i++) {
            const size_t row = (size_t)mtile * 128 + warp_m * 64 + mt * 16 + g + i * 8;
#pragma unroll
            for (int nt = 0; nt < 4; nt++) {
                const uint32_t col = ntile * 128 + warp_n * 32 + nt * 8 + tg * 2;
                *(float2*)&out[row * N_DIM + col] =
                    make_float2(acc[mt][nt][i * 2 + 0], acc[mt][nt][i * 2 + 1]);
            }
        }
}

// ---------------------------------------------------------------------------
// Harness entry
// d_in[0]=data [8,2048,4096] f32, d_in[1]=W [4096,4096] f32,
// d_in[2]=lora_a [8,16,4096] f32, d_in[3]=lora_b [8,4096,16] f32
// ---------------------------------------------------------------------------
extern "C" void kernel_launch(void* const* d_in, const int* in_sizes, int n_in,
                              void* d_out, int out_size) {
    const float* x = (const float*)d_in[0];
    const float* W = (const float*)d_in[1];
    const float* la = (const float*)d_in[2];
    const float* lb = (const float*)d_in[3];
    float* out = (float*)d_out;

    cudaFuncSetAttribute(lora_gemm_kernel,
                         cudaFuncAttributeMaxDynamicSharedMemorySize, SMEM_BYTES);

    lora_t_kernel<<<M_DIM / 32, 256>>>(x, la);
    ext_a_kernel<<<(128 * KT_CNT * 1024) / 256, 256>>>(x);
    ext_b_kernel<<<(32 * KT_CNT * 1024) / 256, 256>>>(W, lb);

    dim3 grid(N_DIM / 128, M_DIM / 128);  // (32, 128)
    lora_gemm_kernel<<<grid, 256, SMEM_BYTES>>>(out);
}